// round 14
// baseline (speedup 1.0000x reference)
#include <cuda_runtime.h>
#include <cuda.h>
#include <cuda_bf16.h>
#include <cstdint>

#define BATCH 4
#define SEQ 2048
#define DMODEL 1024
#define NHEADS 16
#define HDIM 64
#define MROWS (BATCH * SEQ)      // 8192

__device__ uint32_t g_x [MROWS * DMODEL];               // x, tf32 bits
__device__ uint32_t g_wq[DMODEL * DMODEL];
__device__ uint32_t g_wk[DMODEL * DMODEL];
__device__ uint32_t g_wv[DMODEL * DMODEL];
__device__ uint32_t g_wo[DMODEL * DMODEL];
__device__ uint32_t g_q [BATCH * NHEADS * SEQ * HDIM];  // [B,H,S,Dh] tf32 bits
__device__ uint32_t g_k [BATCH * NHEADS * SEQ * HDIM];  // [B,H,S,Dh]
__device__ uint32_t g_v [BATCH * NHEADS * HDIM * SEQ];  // [B,H,Dh,S]  (transposed)
__device__ uint32_t g_ao[BATCH * SEQ * DMODEL];         // [B,S,D] tf32 bits

__device__ __forceinline__ uint32_t f2tf32(float x) {
    uint32_t r;
    asm("cvt.rna.tf32.f32 %0, %1;" : "=r"(r) : "f"(x));
    return r;
}
__device__ __forceinline__ float fexp2(float x) {
    float y;
    asm("ex2.approx.ftz.f32 %0, %1;" : "=f"(y) : "f"(x));
    return y;
}
__device__ __forceinline__ void mma_tf32(float* c, const uint32_t* a, const uint32_t* b) {
    asm volatile(
        "mma.sync.aligned.m16n8k8.row.col.f32.tf32.tf32.f32 "
        "{%0,%1,%2,%3}, {%4,%5,%6,%7}, {%8,%9}, {%0,%1,%2,%3};"
        : "+f"(c[0]), "+f"(c[1]), "+f"(c[2]), "+f"(c[3])
        : "r"(a[0]), "r"(a[1]), "r"(a[2]), "r"(a[3]), "r"(b[0]), "r"(b[1]));
}
__device__ __forceinline__ void ldsm4(uint32_t& r0, uint32_t& r1,
                                      uint32_t& r2, uint32_t& r3, uint32_t addr) {
    asm volatile("ldmatrix.sync.aligned.m8n8.x4.shared.b16 {%0,%1,%2,%3}, [%4];"
                 : "=r"(r0), "=r"(r1), "=r"(r2), "=r"(r3) : "r"(addr));
}
__device__ __forceinline__ uint32_t smem_u32(const void* p) {
    return (uint32_t)__cvta_generic_to_shared(p);
}
// ---- TMA / mbarrier helpers ----
__device__ __forceinline__ void tma2d(uint32_t smem, const CUtensorMap* tmap,
                                      int x, int y, uint32_t mbar) {
    asm volatile(
        "cp.async.bulk.tensor.2d.shared::cta.global.tile.mbarrier::complete_tx::bytes "
        "[%0], [%1, {%2, %3}], [%4];"
        :: "r"(smem), "l"(tmap), "r"(x), "r"(y), "r"(mbar) : "memory");
}
__device__ __forceinline__ void tma3d(uint32_t smem, const CUtensorMap* tmap,
                                      int x, int y, int z, uint32_t mbar) {
    asm volatile(
        "cp.async.bulk.tensor.3d.shared::cta.global.tile.mbarrier::complete_tx::bytes "
        "[%0], [%1, {%2, %3, %4}], [%5];"
        :: "r"(smem), "l"(tmap), "r"(x), "r"(y), "r"(z), "r"(mbar) : "memory");
}
__device__ __forceinline__ void mbar_init(uint32_t mbar, uint32_t cnt) {
    asm volatile("mbarrier.init.shared.b64 [%0], %1;" :: "r"(mbar), "r"(cnt) : "memory");
}
__device__ __forceinline__ void mbar_expect_tx(uint32_t mbar, uint32_t bytes) {
    asm volatile("mbarrier.arrive.expect_tx.shared.b64 _, [%0], %1;"
                 :: "r"(mbar), "r"(bytes) : "memory");
}
__device__ __forceinline__ void mbar_arrive(uint32_t mbar) {
    asm volatile("mbarrier.arrive.shared.b64 _, [%0];" :: "r"(mbar) : "memory");
}
__device__ __forceinline__ void mbar_wait(uint32_t mbar, uint32_t phase) {
    uint32_t ok = 0;
    while (!ok) {
        asm volatile("{\n\t.reg .pred p;\n\t"
                     "mbarrier.try_wait.parity.acquire.cta.shared::cta.b64 p, [%1], %2;\n\t"
                     "selp.b32 %0, 1, 0, p;\n\t}"
                     : "=r"(ok) : "r"(mbar), "r"(phase) : "memory");
    }
}

// ---------------------------------------------------------------------------
// fp32 -> tf32-bits elementwise convert, single fused launch
// ---------------------------------------------------------------------------
#define NX4 (MROWS * DMODEL / 4)
#define NW4 (DMODEL * DMODEL / 4)
__global__ __launch_bounds__(256) void cvt_all_kernel(
    const float4* __restrict__ x,
    const float4* __restrict__ wq, const float4* __restrict__ wk,
    const float4* __restrict__ wv, const float4* __restrict__ wo,
    uint4* __restrict__ ox,
    uint4* __restrict__ oq, uint4* __restrict__ ok,
    uint4* __restrict__ ov, uint4* __restrict__ oo)
{
    const int i = blockIdx.x * blockDim.x + threadIdx.x;
    const float4* src;
    uint4* dst;
    int off;
    if (i < NX4) { src = x; dst = ox; off = i; }
    else {
        const int k = i - NX4;
        const int w = k >> 18;
        off = k & (NW4 - 1);
        src = (w == 0) ? wq : (w == 1) ? wk : (w == 2) ? wv : wo;
        dst = (w == 0) ? oq : (w == 1) ? ok : (w == 2) ? ov : oo;
    }
    float4 v = src[off];
    dst[off] = make_uint4(f2tf32(v.x), f2tf32(v.y), f2tf32(v.z), f2tf32(v.w));
}

// ---------------------------------------------------------------------------
// TMA-fed tf32 GEMM: C = A[M,K] * B[N,K]^T, 128x256 CTA tile, BK=32,
// 4-stage mbarrier pipeline. 8 warps, warp tile 64x64.
// Smem: ctrl 1KB | A 4x16KB | B 4x32KB = 197632 B, 1 CTA/SM.
// ---------------------------------------------------------------------------
#define STA 16384
#define STB 32768
#define NST 4
#define TG_SMEM (1024 + NST * (STA + STB))   // 197632

struct GemmAcc { float a[4][8][4]; };

__device__ __forceinline__ void tma_gemm_core(
    const CUtensorMap* tA, const CUtensorMap* tB, int bm, int bn, GemmAcc& G)
{
    extern __shared__ uint32_t gsm[];
    const uint32_t sb  = smem_u32(gsm);
    const uint32_t stA = sb + 1024;
    const uint32_t stB = sb + 1024 + NST * STA;
    const int tid  = threadIdx.x;
    const int warp = tid >> 5;
    const int lane = tid & 31;
    const int wm = warp >> 2, wn = warp & 3;   // 2 x 4 warps, tile 64x64
    const int g  = lane >> 3, ri = lane & 7;

    if (tid == 0) {
#pragma unroll
        for (int s = 0; s < NST; s++) {
            mbar_init(sb + 64 + 16 * s, 1);
            mbar_init(sb + 160 + 16 * s, 256);
        }
    }
    __syncthreads();
    if (tid == 0) {
#pragma unroll
        for (int s = 0; s < NST; s++) {
            mbar_expect_tx(sb + 64 + 16 * s, STA + STB);
            tma2d(stA + s * STA, tA, s * 32, bm, sb + 64 + 16 * s);
            tma2d(stB + s * STB, tB, s * 32, bn, sb + 64 + 16 * s);
        }
    }

    uint32_t aRow[4], bRow[4];
#pragma unroll
    for (int mt = 0; mt < 4; mt++)
        aRow[mt] = (uint32_t)((wm * 64 + mt * 16 + (g & 1) * 8 + ri) * 128);
#pragma unroll
    for (int np = 0; np < 4; np++)
        bRow[np] = (uint32_t)((wn * 64 + np * 16 + (g >> 1) * 8 + ri) * 128);
    const int asel = g >> 1, bsel = g & 1;

#pragma unroll
    for (int i = 0; i < 4; i++)
#pragma unroll
        for (int j = 0; j < 8; j++)
#pragma unroll
            for (int q = 0; q < 4; q++) G.a[i][j][q] = 0.0f;

    for (int t = 0; t < 32; t++) {
        const int buf = t % NST;
        const uint32_t sA = stA + (uint32_t)buf * STA;
        const uint32_t sBs = stB + (uint32_t)buf * STB;
        mbar_wait(sb + 64 + 16 * buf, (uint32_t)((t / NST) & 1));

#pragma unroll
        for (int ks = 0; ks < 4; ks++) {
            const uint32_t aCh = (uint32_t)(((ks * 2 + asel) ^ ri) * 16);
            const uint32_t bCh = (uint32_t)(((ks * 2 + bsel) ^ ri) * 16);
            uint32_t af[4][4], bf[8][2];
#pragma unroll
            for (int mt = 0; mt < 4; mt++)
                ldsm4(af[mt][0], af[mt][1], af[mt][2], af[mt][3],
                      sA + aRow[mt] + aCh);
#pragma unroll
            for (int np = 0; np < 4; np++)
                ldsm4(bf[2 * np][0], bf[2 * np][1], bf[2 * np + 1][0], bf[2 * np + 1][1],
                      sBs + bRow[np] + bCh);
#pragma unroll
            for (int mt = 0; mt < 4; mt++)
#pragma unroll
                for (int nt = 0; nt < 8; nt++)
                    mma_tf32(G.a[mt][nt], af[mt], bf[nt]);
        }

        mbar_arrive(sb + 160 + 16 * buf);
        if (t + NST < 32 && tid == 0) {
            mbar_wait(sb + 160 + 16 * buf, (uint32_t)((t / NST) & 1));
            mbar_expect_tx(sb + 64 + 16 * buf, STA + STB);
            tma2d(sA,  tA, (t + NST) * 32, bm, sb + 64 + 16 * buf);
            tma2d(sBs, tB, (t + NST) * 32, bn, sb + 64 + 16 * buf);
        }
    }
}

// Fused QKV projection; z selects weight/output. z==2 (V) scatters transposed.
__global__ __launch_bounds__(256, 1) void gemm_qkv_tma(
    const __grid_constant__ CUtensorMap tX,
    const __grid_constant__ CUtensorMap tWq,
    const __grid_constant__ CUtensorMap tWk,
    const __grid_constant__ CUtensorMap tWv,
    uint32_t* __restrict__ Oq, uint32_t* __restrict__ Ok,
    uint32_t* __restrict__ Ov)
{
    const int zi = blockIdx.z;
    const CUtensorMap* tW = (zi == 0) ? &tWq : (zi == 1) ? &tWk : &tWv;
    uint32_t* C = (zi == 0) ? Oq : (zi == 1) ? Ok : Ov;

    const int bm = blockIdx.y << 7;
    const int bn = blockIdx.x << 8;        // 256-wide n tile
    GemmAcc G;
    tma_gemm_core(&tX, tW, bm, bn, G);

    const int lane = threadIdx.x & 31;
    const int warp = threadIdx.x >> 5;
    const int r = lane >> 2, c = lane & 3;
    const int wm = warp >> 2, wn = warp & 3;
#pragma unroll
    for (int mt = 0; mt < 4; mt++) {
        const int m0 = bm + wm * 64 + mt * 16 + r;
#pragma unroll
        for (int nt = 0; nt < 8; nt++) {
            const int n = bn + wn * 64 + nt * 8 + c * 2;
            const int h = n >> 6;
            const int dh = n & 63;
#pragma unroll
            for (int half = 0; half < 2; half++) {
                const int m = m0 + half * 8;
                const int b = m >> 11;
                const int s = m & (SEQ - 1);
                const uint32_t v0 = f2tf32(G.a[mt][nt][half * 2]);
                const uint32_t v1 = f2tf32(G.a[mt][nt][half * 2 + 1]);
                if (zi == 2) {
                    const int base = ((b * NHEADS + h) * HDIM + dh) * SEQ + s;
                    C[base] = v0;
                    C[base + SEQ] = v1;
                } else {
                    *(uint2*)&C[((b * NHEADS + h) * SEQ + s) * HDIM + dh] =
                        make_uint2(v0, v1);
                }
            }
        }
    }
}

__global__ __launch_bounds__(256, 1) void gemm_o_tma(
    const __grid_constant__ CUtensorMap tA,
    const __grid_constant__ CUtensorMap tW,
    float* __restrict__ C)
{
    const int bm = blockIdx.y << 7;
    const int bn = blockIdx.x << 8;
    GemmAcc G;
    tma_gemm_core(&tA, &tW, bm, bn, G);

    const int lane = threadIdx.x & 31;
    const int warp = threadIdx.x >> 5;
    const int r = lane >> 2, c = lane & 3;
    const int wm = warp >> 2, wn = warp & 3;
#pragma unroll
    for (int mt = 0; mt < 4; mt++) {
        const int m0 = bm + wm * 64 + mt * 16 + r;
#pragma unroll
        for (int nt = 0; nt < 8; nt++) {
            const int n = bn + wn * 64 + nt * 8 + c * 2;
#pragma unroll
            for (int half = 0; half < 2; half++) {
                const int m = m0 + half * 8;
                float2 v = make_float2(G.a[mt][nt][half * 2],
                                       G.a[mt][nt][half * 2 + 1]);
                *(float2*)&C[m * DMODEL + n] = v;
            }
        }
    }
}

// ---------------------------------------------------------------------------
// TMA-fed tf32 flash attention (causal), unchanged from R12 (passing).
// ---------------------------------------------------------------------------
#define APS 68
#define AT_KOFF 1024
#define AT_VOFF (1024 + 2 * 16384)
#define AT_POFF (1024 + 4 * 16384)
#define AT_SMEM (AT_POFF + 128 * APS * 4)    // 101376 B
#define QSCALE (0.125f * 1.4426950408889634f)

__global__ __launch_bounds__(256, 2) void attn_tma_kernel(
    const __grid_constant__ CUtensorMap tK,
    const __grid_constant__ CUtensorMap tV,
    const uint32_t* __restrict__ Q, uint32_t* __restrict__ O)
{
    extern __shared__ uint32_t smu[];
    const uint32_t sb = smem_u32(smu);
    uint32_t* Pu = smu + AT_POFF / 4;

    const int tid  = threadIdx.x;
    const int warp = tid >> 5;
    const int lane = tid & 31;
    const int r = lane >> 2;
    const int c = lane & 3;
    const int g  = lane >> 3;
    const int ri = lane & 7;

    const int bh = blockIdx.y;
    const int QT = gridDim.x - 1 - blockIdx.x;    // longest first
    const int q0 = QT << 7;
    const uint32_t* Qb = Q + bh * (SEQ * HDIM);

    if (tid == 0) {
        mbar_init(sb + 64, 1);  mbar_init(sb + 80, 1);
        mbar_init(sb + 128, 256); mbar_init(sb + 144, 256);
    }
    __syncthreads();

    const int T = 2 * QT + 1;
    auto issue_kv = [&](int t) {   // tid 0 only
        const int buf = t & 1;
        const int k0 = t << 6;
        const uint32_t fullb = sb + 64 + 16 * buf;
        mbar_expect_tx(fullb, 32768);
        const uint32_t kst = sb + AT_KOFF + buf * 16384;
        const uint32_t vst = sb + AT_VOFF + buf * 16384;
        tma3d(kst,        &tK, 0,       k0, bh, fullb);
        tma3d(kst + 8192, &tK, 32,      k0, bh, fullb);
        tma3d(vst,        &tV, k0,      0,  bh, fullb);
        tma3d(vst + 8192, &tV, k0 + 32, 0,  bh, fullb);
    };
    if (tid == 0) {
        issue_kv(0);
        issue_kv(1);
    }

    {
        const int qrow = tid >> 1;
        const int qcol = (tid & 1) << 5;
#pragma unroll
        for (int cc = 0; cc < 32; cc += 4)
            *(uint4*)&Pu[qrow * APS + qcol + cc] =
                *(const uint4*)&Qb[(q0 + qrow) * HDIM + qcol + cc];
    }
    __syncthreads();

    const int qr = warp * 16 + r;
    uint32_t qf[8][4];
#pragma unroll
    for (int ks = 0; ks < 8; ks++) {
        const int d = ks * 8 + c;
        qf[ks][0] = f2tf32(QSCALE * __uint_as_float(Pu[qr * APS + d]));
        qf[ks][1] = f2tf32(QSCALE * __uint_as_float(Pu[(qr + 8) * APS + d]));
        qf[ks][2] = f2tf32(QSCALE * __uint_as_float(Pu[qr * APS + d + 4]));
        qf[ks][3] = f2tf32(QSCALE * __uint_as_float(Pu[(qr + 8) * APS + d + 4]));
    }

    uint32_t nRow[4];
#pragma unroll
    for (int np = 0; np < 4; np++)
        nRow[np] = (uint32_t)((np * 16 + (g >> 1) * 8 + ri) * 128);
    const int bsel = g & 1;
    const int offP = ((g & 1) * 8 + ri) * APS + (g >> 1) * 4;
    const uint32_t puB = smem_u32(Pu);

    float oacc[8][4];
#pragma unroll
    for (int nt = 0; nt < 8; nt++)
#pragma unroll
        for (int j = 0; j < 4; j++) oacc[nt][j] = 0.0f;
    float mrun[2] = {-1e30f, -1e30f};
    float lrun[2] = {0.0f, 0.0f};

    for (int t = 0; t <= T; t++) {
        const int buf = t & 1;
        const uint32_t phase = (uint32_t)((t >> 1) & 1);
        mbar_wait(sb + 64 + 16 * buf, phase);

        const uint32_t ktB = sb + AT_KOFF + (uint32_t)buf * 16384;
        const uint32_t vtB = sb + AT_VOFF + (uint32_t)buf * 16384;

        float sacc[8][4];
#pragma unroll
        for (int nt = 0; nt < 8; nt++)
#pragma unroll
            for (int j = 0; j < 4; j++) sacc[nt][j] = 0.0f;
#pragma unroll
        for (int ks = 0; ks < 8; ks++) {
            const uint32_t base = ktB + (uint32_t)((ks >> 2) * 8192);
            const uint32_t ch = (uint32_t)((((2 * ks + bsel) & 7) ^ ri) * 16);
            uint32_t kf[8][2];
#pragma unroll
            for (int np = 0; np < 4; np++)
                ldsm4(kf[2 * np][0], kf[2 * np][1],
                      kf[2 * np + 1][0], kf[2 * np + 1][1],
                      base + nRow[np] + ch);
#pragma unroll
            for (int nt = 0; nt < 8; nt++)
                mma_tf32(sacc[nt], qf[ks], kf[nt]);
        }

        if (t >= 2 * QT) {
            const int kbase = t << 6;
#pragma unroll
            for (int nt = 0; nt < 8; nt++)
#pragma unroll
                for (int j = 0; j < 4; j++) {
                    const int kg = kbase + nt * 8 + 2 * c + (j & 1);
                    const int qg = q0 + warp * 16 + r + (j >> 1) * 8;
                    if (kg > qg) sacc[nt][j] = -1e30f;
                }
        }

#pragma unroll
        for (int hh = 0; hh < 2; hh++) {
            float tm = -1e30f;
#pragma unroll
            for (int nt = 0; nt < 8; nt++)
                tm = fmaxf(tm, fmaxf(sacc[nt][2 * hh], sacc[nt][2 * hh + 1]));
            tm = fmaxf(tm, __shfl_xor_sync(0xffffffffu, tm, 1));
            tm = fmaxf(tm, __shfl_xor_sync(0xffffffffu, tm, 2));
            const float mnew  = fmaxf(mrun[hh], tm);
            const float alpha = fexp2(mrun[hh] - mnew);
            float ls = 0.0f;
            const int prow = (warp * 16 + r + hh * 8) * APS;
#pragma unroll
            for (int nt = 0; nt < 8; nt++) {
                const float p0 = fexp2(sacc[nt][2 * hh] - mnew);
                const float p1 = fexp2(sacc[nt][2 * hh + 1] - mnew);
                ls += p0 + p1;
                uint2 pv = make_uint2(f2tf32(p0), f2tf32(p1));
                *(uint2*)&Pu[prow + nt * 8 + 2 * c] = pv;
            }
            ls += __shfl_xor_sync(0xffffffffu, ls, 1);
            ls += __shfl_xor_sync(0xffffffffu, ls, 2);
            lrun[hh] = lrun[hh] * alpha + ls;
            mrun[hh] = mnew;
#pragma unroll
            for (int nt = 0; nt < 8; nt++) {
                oacc[nt][2 * hh]     *= alpha;
                oacc[nt][2 * hh + 1] *= alpha;
            }
        }
        __syncwarp();

#pragma unroll
        for (int ks = 0; ks < 8; ks++) {
            const uint32_t base = vtB + (uint32_t)((ks >> 2) * 8192);
            const uint32_t ch = (uint32_t)((((2 * ks + bsel) & 7) ^ ri) * 16);
            uint32_t pf[4], vf[8][2];
            ldsm4(pf[0], pf[1], pf[2], pf[3],
                  puB + (uint32_t)(warp * 16 * APS + ks * 8 + offP) * 4u);
#pragma unroll
            for (int np = 0; np < 4; np++)
                ldsm4(vf[2 * np][0], vf[2 * np][1],
                      vf[2 * np + 1][0], vf[2 * np + 1][1],
                      base + nRow[np] + ch);
#pragma unroll
            for (int nt = 0; nt < 8; nt++)
                mma_tf32(oacc[nt], pf, vf[nt]);
        }

        mbar_arrive(sb + 128 + 16 * buf);
        if (tid == 0 && t + 2 <= T) {
            mbar_wait(sb + 128 + 16 * buf, phase);
            issue_kv(t + 2);
        }
    }

    const float rinv0 = 1.0f / lrun[0];
    const float rinv1 = 1.0f / lrun[1];
    const int b = bh >> 4, h = bh & 15;
    const int row0 = q0 + qr;
#pragma unroll
    for (int nt = 0; nt < 8; nt++) {
        const int dh = nt * 8 + 2 * c;
        uint2 v0 = make_uint2(f2tf32(oacc[nt][0] * rinv0), f2tf32(oacc[nt][1] * rinv0));
        uint2 v1 = make_uint2(f2tf32(oacc[nt][2] * rinv1), f2tf32(oacc[nt][3] * rinv1));
        *(uint2*)&O[(b * SEQ + row0) * DMODEL + h * HDIM + dh] = v0;
        *(uint2*)&O[(b * SEQ + row0 + 8) * DMODEL + h * HDIM + dh] = v1;
    }
}

// ---------------------------------------------------------------------------
typedef CUresult (*PFN_encodeTiled)(
    CUtensorMap*, CUtensorMapDataType, cuuint32_t, void*,
    const cuuint64_t*, const cuuint64_t*, const cuuint32_t*, const cuuint32_t*,
    CUtensorMapInterleave, CUtensorMapSwizzle, CUtensorMapL2promotion,
    CUtensorMapFloatOOBfill);

extern "C" void kernel_launch(void* const* d_in, const int* in_sizes, int n_in,
                              void* d_out, int out_size)
{
    const float* x  = (const float*)d_in[0];
    const float* wq = (const float*)d_in[1];
    const float* wk = (const float*)d_in[2];
    const float* wv = (const float*)d_in[3];
    const float* wo = (const float*)d_in[4];
    float* out = (float*)d_out;

    uint32_t *px, *pwq, *pwk, *pwv, *pwo, *pq, *pk, *pv, *pao;
    cudaGetSymbolAddress((void**)&px,  g_x);
    cudaGetSymbolAddress((void**)&pwq, g_wq);
    cudaGetSymbolAddress((void**)&pwk, g_wk);
    cudaGetSymbolAddress((void**)&pwv, g_wv);
    cudaGetSymbolAddress((void**)&pwo, g_wo);
    cudaGetSymbolAddress((void**)&pq,  g_q);
    cudaGetSymbolAddress((void**)&pk,  g_k);
    cudaGetSymbolAddress((void**)&pv,  g_v);
    cudaGetSymbolAddress((void**)&pao, g_ao);

    void* fnp = nullptr;
    cudaDriverEntryPointQueryResult qr;
    cudaGetDriverEntryPointByVersion("cuTensorMapEncodeTiled", &fnp, 12000,
                                     cudaEnableDefault, &qr);
    PFN_encodeTiled enc = (PFN_encodeTiled)fnp;

    CUtensorMap tX, tWq, tWk, tWv, tAO, tWO, tKm, tVm;
    auto mkA = [&](CUtensorMap* m, void* base, cuuint64_t rows) {   // box 32x128
        cuuint64_t dims[2]    = {DMODEL, rows};
        cuuint64_t strides[1] = {DMODEL * 4};
        cuuint32_t box[2]     = {32, 128};
        cuuint32_t es[2]      = {1, 1};
        enc(m, CU_TENSOR_MAP_DATA_TYPE_FLOAT32, 2, base, dims, strides, box, es,
            CU_TENSOR_MAP_INTERLEAVE_NONE, CU_TENSOR_MAP_SWIZZLE_128B,
            CU_TENSOR_MAP_L2_PROMOTION_L2_128B, CU_TENSOR_MAP_FLOAT_OOB_FILL_NONE);
    };
    auto mkB = [&](CUtensorMap* m, void* base, cuuint64_t rows) {   // box 32x256
        cuuint64_t dims[2]    = {DMODEL, rows};
        cuuint64_t strides[1] = {DMODEL * 4};
        cuuint32_t box[2]     = {32, 256};
        cuuint32_t es[2]      = {1, 1};
        enc(m, CU_TENSOR_MAP_DATA_TYPE_FLOAT32, 2, base, dims, strides, box, es,
            CU_TENSOR_MAP_INTERLEAVE_NONE, CU_TENSOR_MAP_SWIZZLE_128B,
            CU_TENSOR_MAP_L2_PROMOTION_L2_128B, CU_TENSOR_MAP_FLOAT_OOB_FILL_NONE);
    };
    mkA(&tX,  px,  MROWS);
    mkB(&tWq, pwq, DMODEL);
    mkB(&tWk, pwk, DMODEL);
    mkB(&tWv, pwv, DMODEL);
    mkA(&tAO, pao, MROWS);
    mkB(&tWO, pwo, DMODEL);
    {   // K: [BH][S][Dh], box (dh=32, s=64)
        cuuint64_t dims[3]    = {HDIM, SEQ, BATCH * NHEADS};
        cuuint64_t strides[2] = {HDIM * 4, (cuuint64_t)SEQ * HDIM * 4};
        cuuint32_t box[3]     = {32, 64, 1};
        cuuint32_t es[3]      = {1, 1, 1};
        enc(&tKm, CU_TENSOR_MAP_DATA_TYPE_FLOAT32, 3, pk, dims, strides, box, es,
            CU_TENSOR_MAP_INTERLEAVE_NONE, CU_TENSOR_MAP_SWIZZLE_128B,
            CU_TENSOR_MAP_L2_PROMOTION_L2_128B, CU_TENSOR_MAP_FLOAT_OOB_FILL_NONE);
    }
    {   // V: [BH][Dh][S], box (s=32, dh=64)
        cuuint64_t dims[3]    = {SEQ, HDIM, BATCH * NHEADS};
        cuuint64_t strides[2] = {SEQ * 4, (cuuint64_t)SEQ * HDIM * 4};
        cuuint32_t box[3]     = {32, 64, 1};
        cuuint32_t es[3]      = {1, 1, 1};
        enc(&tVm, CU_TENSOR_MAP_DATA_TYPE_FLOAT32, 3, pv, dims, strides, box, es,
            CU_TENSOR_MAP_INTERLEAVE_NONE, CU_TENSOR_MAP_SWIZZLE_128B,
            CU_TENSOR_MAP_L2_PROMOTION_L2_128B, CU_TENSOR_MAP_FLOAT_OOB_FILL_NONE);
    }

    cudaFuncSetAttribute(gemm_qkv_tma, cudaFuncAttributeMaxDynamicSharedMemorySize, TG_SMEM);
    cudaFuncSetAttribute(gemm_o_tma,   cudaFuncAttributeMaxDynamicSharedMemorySize, TG_SMEM);
    cudaFuncSetAttribute(attn_tma_kernel, cudaFuncAttributeMaxDynamicSharedMemorySize, AT_SMEM);

    const int total4 = NX4 + 4 * NW4;
    cvt_all_kernel<<<total4 / 256, 256>>>(
        (const float4*)x, (const float4*)wq, (const float4*)wk,
        (const float4*)wv, (const float4*)wo,
        (uint4*)px, (uint4*)pwq, (uint4*)pwk, (uint4*)pwv, (uint4*)pwo);

    const dim3 qkv_grid(DMODEL / 256, MROWS / 128, 3);   // (4, 64, 3)
    gemm_qkv_tma<<<qkv_grid, 256, TG_SMEM>>>(tX, tWq, tWk, tWv, pq, pk, pv);

    const dim3 agrid(SEQ / 128, BATCH * NHEADS);         // (16, 64)
    attn_tma_kernel<<<agrid, 256, AT_SMEM>>>(tKm, tVm, pq, pao);

    const dim3 ogrid(DMODEL / 256, MROWS / 128);         // (4, 64)
    gemm_o_tma<<<ogrid, 256, TG_SMEM>>>(tAO, tWO, out);
}

// round 15
// speedup vs baseline: 1.0135x; 1.0135x over previous
#include <cuda_runtime.h>
#include <cuda.h>
#include <cuda_bf16.h>
#include <cstdint>

#define BATCH 4
#define SEQ 2048
#define DMODEL 1024
#define NHEADS 16
#define HDIM 64
#define MROWS (BATCH * SEQ)      // 8192

__device__ uint32_t g_x [MROWS * DMODEL];               // x, tf32 bits
__device__ uint32_t g_wq[DMODEL * DMODEL];
__device__ uint32_t g_wk[DMODEL * DMODEL];
__device__ uint32_t g_wv[DMODEL * DMODEL];
__device__ uint32_t g_wo[DMODEL * DMODEL];
__device__ uint32_t g_q [BATCH * NHEADS * SEQ * HDIM];  // [B,H,S,Dh] tf32 bits
__device__ uint32_t g_k [BATCH * NHEADS * SEQ * HDIM];  // [B,H,S,Dh]
__device__ uint32_t g_v [BATCH * NHEADS * HDIM * SEQ];  // [B,H,Dh,S]  (transposed)
__device__ uint32_t g_ao[BATCH * SEQ * DMODEL];         // [B,S,D] tf32 bits

__device__ __forceinline__ uint32_t f2tf32(float x) {
    uint32_t r;
    asm("cvt.rna.tf32.f32 %0, %1;" : "=r"(r) : "f"(x));
    return r;
}
__device__ __forceinline__ float fexp2(float x) {
    float y;
    asm("ex2.approx.ftz.f32 %0, %1;" : "=f"(y) : "f"(x));
    return y;
}
__device__ __forceinline__ void mma_tf32(float* c, const uint32_t* a, const uint32_t* b) {
    asm volatile(
        "mma.sync.aligned.m16n8k8.row.col.f32.tf32.tf32.f32 "
        "{%0,%1,%2,%3}, {%4,%5,%6,%7}, {%8,%9}, {%0,%1,%2,%3};"
        : "+f"(c[0]), "+f"(c[1]), "+f"(c[2]), "+f"(c[3])
        : "r"(a[0]), "r"(a[1]), "r"(a[2]), "r"(a[3]), "r"(b[0]), "r"(b[1]));
}
__device__ __forceinline__ void ldsm4(uint32_t& r0, uint32_t& r1,
                                      uint32_t& r2, uint32_t& r3, uint32_t addr) {
    asm volatile("ldmatrix.sync.aligned.m8n8.x4.shared.b16 {%0,%1,%2,%3}, [%4];"
                 : "=r"(r0), "=r"(r1), "=r"(r2), "=r"(r3) : "r"(addr));
}
__device__ __forceinline__ uint32_t smem_u32(const void* p) {
    return (uint32_t)__cvta_generic_to_shared(p);
}
// ---- TMA / mbarrier helpers ----
__device__ __forceinline__ void tma2d(uint32_t smem, const CUtensorMap* tmap,
                                      int x, int y, uint32_t mbar) {
    asm volatile(
        "cp.async.bulk.tensor.2d.shared::cta.global.tile.mbarrier::complete_tx::bytes "
        "[%0], [%1, {%2, %3}], [%4];"
        :: "r"(smem), "l"(tmap), "r"(x), "r"(y), "r"(mbar) : "memory");
}
__device__ __forceinline__ void tma3d(uint32_t smem, const CUtensorMap* tmap,
                                      int x, int y, int z, uint32_t mbar) {
    asm volatile(
        "cp.async.bulk.tensor.3d.shared::cta.global.tile.mbarrier::complete_tx::bytes "
        "[%0], [%1, {%2, %3, %4}], [%5];"
        :: "r"(smem), "l"(tmap), "r"(x), "r"(y), "r"(z), "r"(mbar) : "memory");
}
__device__ __forceinline__ void mbar_init(uint32_t mbar, uint32_t cnt) {
    asm volatile("mbarrier.init.shared.b64 [%0], %1;" :: "r"(mbar), "r"(cnt) : "memory");
}
__device__ __forceinline__ void mbar_expect_tx(uint32_t mbar, uint32_t bytes) {
    asm volatile("mbarrier.arrive.expect_tx.shared.b64 _, [%0], %1;"
                 :: "r"(mbar), "r"(bytes) : "memory");
}
__device__ __forceinline__ void mbar_arrive(uint32_t mbar) {
    asm volatile("mbarrier.arrive.shared.b64 _, [%0];" :: "r"(mbar) : "memory");
}
__device__ __forceinline__ void mbar_wait(uint32_t mbar, uint32_t phase) {
    uint32_t ok = 0;
    while (!ok) {
        asm volatile("{\n\t.reg .pred p;\n\t"
                     "mbarrier.try_wait.parity.acquire.cta.shared::cta.b64 p, [%1], %2;\n\t"
                     "selp.b32 %0, 1, 0, p;\n\t}"
                     : "=r"(ok) : "r"(mbar), "r"(phase) : "memory");
    }
}

// ---------------------------------------------------------------------------
// fp32 -> tf32-bits elementwise convert, single fused launch
// ---------------------------------------------------------------------------
#define NX4 (MROWS * DMODEL / 4)
#define NW4 (DMODEL * DMODEL / 4)
__global__ __launch_bounds__(256) void cvt_all_kernel(
    const float4* __restrict__ x,
    const float4* __restrict__ wq, const float4* __restrict__ wk,
    const float4* __restrict__ wv, const float4* __restrict__ wo,
    uint4* __restrict__ ox,
    uint4* __restrict__ oq, uint4* __restrict__ ok,
    uint4* __restrict__ ov, uint4* __restrict__ oo)
{
    const int i = blockIdx.x * blockDim.x + threadIdx.x;
    const float4* src;
    uint4* dst;
    int off;
    if (i < NX4) { src = x; dst = ox; off = i; }
    else {
        const int k = i - NX4;
        const int w = k >> 18;
        off = k & (NW4 - 1);
        src = (w == 0) ? wq : (w == 1) ? wk : (w == 2) ? wv : wo;
        dst = (w == 0) ? oq : (w == 1) ? ok : (w == 2) ? ov : oo;
    }
    float4 v = src[off];
    dst[off] = make_uint4(f2tf32(v.x), f2tf32(v.y), f2tf32(v.z), f2tf32(v.w));
}

// ---------------------------------------------------------------------------
// TMA-fed tf32 GEMM (R12 config): 128x128 tile, BK=32, 3-stage mbarrier.
// Early buffer release: empty-arrive right after the final ldsm batch.
// ---------------------------------------------------------------------------
#define STAGEB 16384
#define TG_SMEM (1024 + 6 * STAGEB)

struct GemmAcc { float a[4][4][4]; };

__device__ __forceinline__ void tma_gemm_core(
    const CUtensorMap* tA, const CUtensorMap* tB, int bm, int bn, GemmAcc& G)
{
    extern __shared__ uint32_t gsm[];
    const uint32_t sb  = smem_u32(gsm);
    const uint32_t stA = sb + 1024;
    const uint32_t stB = sb + 1024 + 3 * STAGEB;
    const int tid  = threadIdx.x;
    const int warp = tid >> 5;
    const int lane = tid & 31;
    const int wm = warp >> 2, wn = warp & 3;
    const int g  = lane >> 3, ri = lane & 7;

    if (tid == 0) {
#pragma unroll
        for (int s = 0; s < 3; s++) {
            mbar_init(sb + 64 + 16 * s, 1);
            mbar_init(sb + 160 + 16 * s, 256);
        }
    }
    __syncthreads();
    if (tid == 0) {
#pragma unroll
        for (int s = 0; s < 3; s++) {
            mbar_expect_tx(sb + 64 + 16 * s, 2 * STAGEB);
            tma2d(stA + s * STAGEB, tA, s * 32, bm, sb + 64 + 16 * s);
            tma2d(stB + s * STAGEB, tB, s * 32, bn, sb + 64 + 16 * s);
        }
    }

    uint32_t aRow[4], bRow[2];
#pragma unroll
    for (int mt = 0; mt < 4; mt++)
        aRow[mt] = (uint32_t)((wm * 64 + mt * 16 + (g & 1) * 8 + ri) * 128);
#pragma unroll
    for (int np = 0; np < 2; np++)
        bRow[np] = (uint32_t)((wn * 32 + np * 16 + (g >> 1) * 8 + ri) * 128);
    const int asel = g >> 1, bsel = g & 1;

#pragma unroll
    for (int i = 0; i < 4; i++)
#pragma unroll
        for (int j = 0; j < 4; j++)
#pragma unroll
            for (int q = 0; q < 4; q++) G.a[i][j][q] = 0.0f;

    for (int t = 0; t < 32; t++) {
        const int buf = t % 3;
        const uint32_t sA = stA + (uint32_t)buf * STAGEB;
        const uint32_t sBs = stB + (uint32_t)buf * STAGEB;
        mbar_wait(sb + 64 + 16 * buf, (uint32_t)((t / 3) & 1));

#pragma unroll
        for (int ks = 0; ks < 4; ks++) {
            const uint32_t aCh = (uint32_t)(((ks * 2 + asel) ^ ri) * 16);
            const uint32_t bCh = (uint32_t)(((ks * 2 + bsel) ^ ri) * 16);
            uint32_t af[4][4], bf[4][2];
#pragma unroll
            for (int mt = 0; mt < 4; mt++)
                ldsm4(af[mt][0], af[mt][1], af[mt][2], af[mt][3],
                      sA + aRow[mt] + aCh);
#pragma unroll
            for (int np = 0; np < 2; np++)
                ldsm4(bf[2 * np][0], bf[2 * np][1], bf[2 * np + 1][0], bf[2 * np + 1][1],
                      sBs + bRow[np] + bCh);
            if (ks == 3)   // buffer fully read: release early, before final mmas
                mbar_arrive(sb + 160 + 16 * buf);
#pragma unroll
            for (int mt = 0; mt < 4; mt++)
#pragma unroll
                for (int nt = 0; nt < 4; nt++)
                    mma_tf32(G.a[mt][nt], af[mt], bf[nt]);
        }

        if (t + 3 < 32 && tid == 0) {
            mbar_wait(sb + 160 + 16 * buf, (uint32_t)((t / 3) & 1));
            mbar_expect_tx(sb + 64 + 16 * buf, 2 * STAGEB);
            tma2d(sA,  tA, (t + 3) * 32, bm, sb + 64 + 16 * buf);
            tma2d(sBs, tB, (t + 3) * 32, bn, sb + 64 + 16 * buf);
        }
    }
}

__global__ __launch_bounds__(256, 2) void gemm_qkv_tma(
    const __grid_constant__ CUtensorMap tX,
    const __grid_constant__ CUtensorMap tWq,
    const __grid_constant__ CUtensorMap tWk,
    const __grid_constant__ CUtensorMap tWv,
    uint32_t* __restrict__ Oq, uint32_t* __restrict__ Ok,
    uint32_t* __restrict__ Ov)
{
    const int zi = blockIdx.z;
    const CUtensorMap* tW = (zi == 0) ? &tWq : (zi == 1) ? &tWk : &tWv;
    uint32_t* C = (zi == 0) ? Oq : (zi == 1) ? Ok : Ov;

    const int bm = blockIdx.y << 7;
    const int bn = blockIdx.x << 7;
    GemmAcc G;
    tma_gemm_core(&tX, tW, bm, bn, G);

    const int lane = threadIdx.x & 31;
    const int warp = threadIdx.x >> 5;
    const int r = lane >> 2, c = lane & 3;
    const int wm = warp >> 2, wn = warp & 3;
#pragma unroll
    for (int mt = 0; mt < 4; mt++) {
        const int m0 = bm + wm * 64 + mt * 16 + r;
#pragma unroll
        for (int nt = 0; nt < 4; nt++) {
            const int n = bn + wn * 32 + nt * 8 + c * 2;
            const int h = n >> 6;
            const int dh = n & 63;
#pragma unroll
            for (int half = 0; half < 2; half++) {
                const int m = m0 + half * 8;
                const int b = m >> 11;
                const int s = m & (SEQ - 1);
                const uint32_t v0 = f2tf32(G.a[mt][nt][half * 2]);
                const uint32_t v1 = f2tf32(G.a[mt][nt][half * 2 + 1]);
                if (zi == 2) {
                    const int base = ((b * NHEADS + h) * HDIM + dh) * SEQ + s;
                    C[base] = v0;
                    C[base + SEQ] = v1;
                } else {
                    *(uint2*)&C[((b * NHEADS + h) * SEQ + s) * HDIM + dh] =
                        make_uint2(v0, v1);
                }
            }
        }
    }
}

__global__ __launch_bounds__(256, 2) void gemm_o_tma(
    const __grid_constant__ CUtensorMap tA,
    const __grid_constant__ CUtensorMap tW,
    float* __restrict__ C)
{
    const int bm = blockIdx.y << 7;
    const int bn = blockIdx.x << 7;
    GemmAcc G;
    tma_gemm_core(&tA, &tW, bm, bn, G);

    const int lane = threadIdx.x & 31;
    const int warp = threadIdx.x >> 5;
    const int r = lane >> 2, c = lane & 3;
    const int wm = warp >> 2, wn = warp & 3;
#pragma unroll
    for (int mt = 0; mt < 4; mt++) {
        const int m0 = bm + wm * 64 + mt * 16 + r;
#pragma unroll
        for (int nt = 0; nt < 4; nt++) {
            const int n = bn + wn * 32 + nt * 8 + c * 2;
#pragma unroll
            for (int half = 0; half < 2; half++) {
                const int m = m0 + half * 8;
                float2 v = make_float2(G.a[mt][nt][half * 2],
                                       G.a[mt][nt][half * 2 + 1]);
                *(float2*)&C[m * DMODEL + n] = v;
            }
        }
    }
}

// ---------------------------------------------------------------------------
// TMA-fed tf32 flash attention (causal), R12 config with early buffer release.
// ---------------------------------------------------------------------------
#define APS 68
#define AT_KOFF 1024
#define AT_VOFF (1024 + 2 * 16384)
#define AT_POFF (1024 + 4 * 16384)
#define AT_SMEM (AT_POFF + 128 * APS * 4)    // 101376 B
#define QSCALE (0.125f * 1.4426950408889634f)

__global__ __launch_bounds__(256, 2) void attn_tma_kernel(
    const __grid_constant__ CUtensorMap tK,
    const __grid_constant__ CUtensorMap tV,
    const uint32_t* __restrict__ Q, uint32_t* __restrict__ O)
{
    extern __shared__ uint32_t smu[];
    const uint32_t sb = smem_u32(smu);
    uint32_t* Pu = smu + AT_POFF / 4;

    const int tid  = threadIdx.x;
    const int warp = tid >> 5;
    const int lane = tid & 31;
    const int r = lane >> 2;
    const int c = lane & 3;
    const int g  = lane >> 3;
    const int ri = lane & 7;

    const int bh = blockIdx.y;
    const int QT = gridDim.x - 1 - blockIdx.x;    // longest first
    const int q0 = QT << 7;
    const uint32_t* Qb = Q + bh * (SEQ * HDIM);

    if (tid == 0) {
        mbar_init(sb + 64, 1);  mbar_init(sb + 80, 1);
        mbar_init(sb + 128, 256); mbar_init(sb + 144, 256);
    }
    __syncthreads();

    const int T = 2 * QT + 1;
    auto issue_kv = [&](int t) {   // tid 0 only
        const int buf = t & 1;
        const int k0 = t << 6;
        const uint32_t fullb = sb + 64 + 16 * buf;
        mbar_expect_tx(fullb, 32768);
        const uint32_t kst = sb + AT_KOFF + buf * 16384;
        const uint32_t vst = sb + AT_VOFF + buf * 16384;
        tma3d(kst,        &tK, 0,       k0, bh, fullb);
        tma3d(kst + 8192, &tK, 32,      k0, bh, fullb);
        tma3d(vst,        &tV, k0,      0,  bh, fullb);
        tma3d(vst + 8192, &tV, k0 + 32, 0,  bh, fullb);
    };
    if (tid == 0) {
        issue_kv(0);
        issue_kv(1);
    }

    {
        const int qrow = tid >> 1;
        const int qcol = (tid & 1) << 5;
#pragma unroll
        for (int cc = 0; cc < 32; cc += 4)
            *(uint4*)&Pu[qrow * APS + qcol + cc] =
                *(const uint4*)&Qb[(q0 + qrow) * HDIM + qcol + cc];
    }
    __syncthreads();

    const int qr = warp * 16 + r;
    uint32_t qf[8][4];
#pragma unroll
    for (int ks = 0; ks < 8; ks++) {
        const int d = ks * 8 + c;
        qf[ks][0] = f2tf32(QSCALE * __uint_as_float(Pu[qr * APS + d]));
        qf[ks][1] = f2tf32(QSCALE * __uint_as_float(Pu[(qr + 8) * APS + d]));
        qf[ks][2] = f2tf32(QSCALE * __uint_as_float(Pu[qr * APS + d + 4]));
        qf[ks][3] = f2tf32(QSCALE * __uint_as_float(Pu[(qr + 8) * APS + d + 4]));
    }

    uint32_t nRow[4];
#pragma unroll
    for (int np = 0; np < 4; np++)
        nRow[np] = (uint32_t)((np * 16 + (g >> 1) * 8 + ri) * 128);
    const int bsel = g & 1;
    const int offP = ((g & 1) * 8 + ri) * APS + (g >> 1) * 4;
    const uint32_t puB = smem_u32(Pu);

    float oacc[8][4];
#pragma unroll
    for (int nt = 0; nt < 8; nt++)
#pragma unroll
        for (int j = 0; j < 4; j++) oacc[nt][j] = 0.0f;
    float mrun[2] = {-1e30f, -1e30f};
    float lrun[2] = {0.0f, 0.0f};

    for (int t = 0; t <= T; t++) {
        const int buf = t & 1;
        const uint32_t phase = (uint32_t)((t >> 1) & 1);
        mbar_wait(sb + 64 + 16 * buf, phase);

        const uint32_t ktB = sb + AT_KOFF + (uint32_t)buf * 16384;
        const uint32_t vtB = sb + AT_VOFF + (uint32_t)buf * 16384;

        // ---- scores (log2-scaled): S = Q K^T ----
        float sacc[8][4];
#pragma unroll
        for (int nt = 0; nt < 8; nt++)
#pragma unroll
            for (int j = 0; j < 4; j++) sacc[nt][j] = 0.0f;
#pragma unroll
        for (int ks = 0; ks < 8; ks++) {
            const uint32_t base = ktB + (uint32_t)((ks >> 2) * 8192);
            const uint32_t ch = (uint32_t)((((2 * ks + bsel) & 7) ^ ri) * 16);
            uint32_t kf[8][2];
#pragma unroll
            for (int np = 0; np < 4; np++)
                ldsm4(kf[2 * np][0], kf[2 * np][1],
                      kf[2 * np + 1][0], kf[2 * np + 1][1],
                      base + nRow[np] + ch);
#pragma unroll
            for (int nt = 0; nt < 8; nt++)
                mma_tf32(sacc[nt], qf[ks], kf[nt]);
        }

        // ---- causal mask (diagonal region only) ----
        if (t >= 2 * QT) {
            const int kbase = t << 6;
#pragma unroll
            for (int nt = 0; nt < 8; nt++)
#pragma unroll
                for (int j = 0; j < 4; j++) {
                    const int kg = kbase + nt * 8 + 2 * c + (j & 1);
                    const int qg = q0 + warp * 16 + r + (j >> 1) * 8;
                    if (kg > qg) sacc[nt][j] = -1e30f;
                }
        }

        // ---- online softmax (base 2, MUFU ex2) ----
#pragma unroll
        for (int hh = 0; hh < 2; hh++) {
            float tm = -1e30f;
#pragma unroll
            for (int nt = 0; nt < 8; nt++)
                tm = fmaxf(tm, fmaxf(sacc[nt][2 * hh], sacc[nt][2 * hh + 1]));
            tm = fmaxf(tm, __shfl_xor_sync(0xffffffffu, tm, 1));
            tm = fmaxf(tm, __shfl_xor_sync(0xffffffffu, tm, 2));
            const float mnew  = fmaxf(mrun[hh], tm);
            const float alpha = fexp2(mrun[hh] - mnew);
            float ls = 0.0f;
            const int prow = (warp * 16 + r + hh * 8) * APS;
#pragma unroll
            for (int nt = 0; nt < 8; nt++) {
                const float p0 = fexp2(sacc[nt][2 * hh] - mnew);
                const float p1 = fexp2(sacc[nt][2 * hh + 1] - mnew);
                ls += p0 + p1;
                uint2 pv = make_uint2(f2tf32(p0), f2tf32(p1));
                *(uint2*)&Pu[prow + nt * 8 + 2 * c] = pv;
            }
            ls += __shfl_xor_sync(0xffffffffu, ls, 1);
            ls += __shfl_xor_sync(0xffffffffu, ls, 2);
            lrun[hh] = lrun[hh] * alpha + ls;
            mrun[hh] = mnew;
#pragma unroll
            for (int nt = 0; nt < 8; nt++) {
                oacc[nt][2 * hh]     *= alpha;
                oacc[nt][2 * hh + 1] *= alpha;
            }
        }
        __syncwarp();   // P region is warp-local: order STS before LDSM

        // ---- O += P V (early release after final V ldsm) ----
#pragma unroll
        for (int ks = 0; ks < 8; ks++) {
            const uint32_t base = vtB + (uint32_t)((ks >> 2) * 8192);
            const uint32_t ch = (uint32_t)((((2 * ks + bsel) & 7) ^ ri) * 16);
            uint32_t pf[4], vf[8][2];
            ldsm4(pf[0], pf[1], pf[2], pf[3],
                  puB + (uint32_t)(warp * 16 * APS + ks * 8 + offP) * 4u);
#pragma unroll
            for (int np = 0; np < 4; np++)
                ldsm4(vf[2 * np][0], vf[2 * np][1],
                      vf[2 * np + 1][0], vf[2 * np + 1][1],
                      base + nRow[np] + ch);
            if (ks == 7)   // K/V buffer fully read: release before final mmas
                mbar_arrive(sb + 128 + 16 * buf);
#pragma unroll
            for (int nt = 0; nt < 8; nt++)
                mma_tf32(oacc[nt], pf, vf[nt]);
        }

        if (tid == 0 && t + 2 <= T) {
            mbar_wait(sb + 128 + 16 * buf, phase);
            issue_kv(t + 2);
        }
    }

    const float rinv0 = 1.0f / lrun[0];
    const float rinv1 = 1.0f / lrun[1];
    const int b = bh >> 4, h = bh & 15;
    const int row0 = q0 + qr;
#pragma unroll
    for (int nt = 0; nt < 8; nt++) {
        const int dh = nt * 8 + 2 * c;
        uint2 v0 = make_uint2(f2tf32(oacc[nt][0] * rinv0), f2tf32(oacc[nt][1] * rinv0));
        uint2 v1 = make_uint2(f2tf32(oacc[nt][2] * rinv1), f2tf32(oacc[nt][3] * rinv1));
        *(uint2*)&O[(b * SEQ + row0) * DMODEL + h * HDIM + dh] = v0;
        *(uint2*)&O[(b * SEQ + row0 + 8) * DMODEL + h * HDIM + dh] = v1;
    }
}

// ---------------------------------------------------------------------------
typedef CUresult (*PFN_encodeTiled)(
    CUtensorMap*, CUtensorMapDataType, cuuint32_t, void*,
    const cuuint64_t*, const cuuint64_t*, const cuuint32_t*, const cuuint32_t*,
    CUtensorMapInterleave, CUtensorMapSwizzle, CUtensorMapL2promotion,
    CUtensorMapFloatOOBfill);

extern "C" void kernel_launch(void* const* d_in, const int* in_sizes, int n_in,
                              void* d_out, int out_size)
{
    const float* x  = (const float*)d_in[0];
    const float* wq = (const float*)d_in[1];
    const float* wk = (const float*)d_in[2];
    const float* wv = (const float*)d_in[3];
    const float* wo = (const float*)d_in[4];
    float* out = (float*)d_out;

    uint32_t *px, *pwq, *pwk, *pwv, *pwo, *pq, *pk, *pv, *pao;
    cudaGetSymbolAddress((void**)&px,  g_x);
    cudaGetSymbolAddress((void**)&pwq, g_wq);
    cudaGetSymbolAddress((void**)&pwk, g_wk);
    cudaGetSymbolAddress((void**)&pwv, g_wv);
    cudaGetSymbolAddress((void**)&pwo, g_wo);
    cudaGetSymbolAddress((void**)&pq,  g_q);
    cudaGetSymbolAddress((void**)&pk,  g_k);
    cudaGetSymbolAddress((void**)&pv,  g_v);
    cudaGetSymbolAddress((void**)&pao, g_ao);

    void* fnp = nullptr;
    cudaDriverEntryPointQueryResult qr;
    cudaGetDriverEntryPointByVersion("cuTensorMapEncodeTiled", &fnp, 12000,
                                     cudaEnableDefault, &qr);
    PFN_encodeTiled enc = (PFN_encodeTiled)fnp;

    CUtensorMap tX, tWq, tWk, tWv, tAO, tWO, tKm, tVm;
    auto mk2 = [&](CUtensorMap* m, void* base, cuuint64_t rows) {
        cuuint64_t dims[2]    = {DMODEL, rows};
        cuuint64_t strides[1] = {DMODEL * 4};
        cuuint32_t box[2]     = {32, 128};
        cuuint32_t es[2]      = {1, 1};
        enc(m, CU_TENSOR_MAP_DATA_TYPE_FLOAT32, 2, base, dims, strides, box, es,
            CU_TENSOR_MAP_INTERLEAVE_NONE, CU_TENSOR_MAP_SWIZZLE_128B,
            CU_TENSOR_MAP_L2_PROMOTION_L2_128B, CU_TENSOR_MAP_FLOAT_OOB_FILL_NONE);
    };
    mk2(&tX,  px,  MROWS);
    mk2(&tWq, pwq, DMODEL);
    mk2(&tWk, pwk, DMODEL);
    mk2(&tWv, pwv, DMODEL);
    mk2(&tAO, pao, MROWS);
    mk2(&tWO, pwo, DMODEL);
    {   // K: [BH][S][Dh], box (dh=32, s=64)
        cuuint64_t dims[3]    = {HDIM, SEQ, BATCH * NHEADS};
        cuuint64_t strides[2] = {HDIM * 4, (cuuint64_t)SEQ * HDIM * 4};
        cuuint32_t box[3]     = {32, 64, 1};
        cuuint32_t es[3]      = {1, 1, 1};
        enc(&tKm, CU_TENSOR_MAP_DATA_TYPE_FLOAT32, 3, pk, dims, strides, box, es,
            CU_TENSOR_MAP_INTERLEAVE_NONE, CU_TENSOR_MAP_SWIZZLE_128B,
            CU_TENSOR_MAP_L2_PROMOTION_L2_128B, CU_TENSOR_MAP_FLOAT_OOB_FILL_NONE);
    }
    {   // V: [BH][Dh][S], box (s=32, dh=64)
        cuuint64_t dims[3]    = {SEQ, HDIM, BATCH * NHEADS};
        cuuint64_t strides[2] = {SEQ * 4, (cuuint64_t)SEQ * HDIM * 4};
        cuuint32_t box[3]     = {32, 64, 1};
        cuuint32_t es[3]      = {1, 1, 1};
        enc(&tVm, CU_TENSOR_MAP_DATA_TYPE_FLOAT32, 3, pv, dims, strides, box, es,
            CU_TENSOR_MAP_INTERLEAVE_NONE, CU_TENSOR_MAP_SWIZZLE_128B,
            CU_TENSOR_MAP_L2_PROMOTION_L2_128B, CU_TENSOR_MAP_FLOAT_OOB_FILL_NONE);
    }

    cudaFuncSetAttribute(gemm_qkv_tma, cudaFuncAttributeMaxDynamicSharedMemorySize, TG_SMEM);
    cudaFuncSetAttribute(gemm_o_tma,   cudaFuncAttributeMaxDynamicSharedMemorySize, TG_SMEM);
    cudaFuncSetAttribute(attn_tma_kernel, cudaFuncAttributeMaxDynamicSharedMemorySize, AT_SMEM);

    const int total4 = NX4 + 4 * NW4;
    cvt_all_kernel<<<total4 / 256, 256>>>(
        (const float4*)x, (const float4*)wq, (const float4*)wk,
        (const float4*)wv, (const float4*)wo,
        (uint4*)px, (uint4*)pwq, (uint4*)pwk, (uint4*)pwv, (uint4*)pwo);

    const dim3 qkv_grid(DMODEL / 128, MROWS / 128, 3);   // (8, 64, 3)
    gemm_qkv_tma<<<qkv_grid, 256, TG_SMEM>>>(tX, tWq, tWk, tWv, pq, pk, pv);

    const dim3 agrid(SEQ / 128, BATCH * NHEADS);         // (16, 64)
    attn_tma_kernel<<<agrid, 256, AT_SMEM>>>(tKm, tVm, pq, pao);

    const dim3 ogrid(DMODEL / 128, MROWS / 128);         // (8, 64)
    gemm_o_tma<<<ogrid, 256, TG_SMEM>>>(tAO, tWO, out);
}